// round 16
// baseline (speedup 1.0000x reference)
#include <cuda_runtime.h>
#include <cuda_bf16.h>

// Problem constants (from reference setup_inputs)
#define Bc 2
#define Tc 2048
#define Dc 1024
#define Nc 16
#define Lc 16
#define Cc 128                 // Tc / Lc
#define S_TOT (Bc*Dc*Nc)       // 32768 states
#define PQ_TOT (Cc*S_TOT)      // 4,194,304

// Scratch (static device arrays — no allocation allowed)
__device__ float g_P[PQ_TOT];
__device__ float g_Q[PQ_TOT];
__device__ float g_H0[PQ_TOT];

// ---- packed f32x2 helpers (sm_103a) ---------------------------------------
typedef unsigned long long f32x2;
__device__ __forceinline__ f32x2 pk2(float lo, float hi) {
    f32x2 r; asm("mov.b64 %0, {%1, %2};" : "=l"(r) : "f"(lo), "f"(hi)); return r;
}
__device__ __forceinline__ void upk2(f32x2 v, float& lo, float& hi) {
    asm("mov.b64 {%0, %1}, %2;" : "=f"(lo), "=f"(hi) : "l"(v));
}
__device__ __forceinline__ f32x2 mul2(f32x2 a, f32x2 b) {
    f32x2 r; asm("mul.rn.f32x2 %0, %1, %2;" : "=l"(r) : "l"(a), "l"(b)); return r;
}
__device__ __forceinline__ f32x2 add2(f32x2 a, f32x2 b) {
    f32x2 r; asm("add.rn.f32x2 %0, %1, %2;" : "=l"(r) : "l"(a), "l"(b)); return r;
}
__device__ __forceinline__ f32x2 fma2(f32x2 a, f32x2 b, f32x2 c) {
    f32x2 r; asm("fma.rn.f32x2 %0, %1, %2, %3;" : "=l"(r) : "l"(a), "l"(b), "l"(c)); return r;
}

union V4U2 { float4 f4; ulonglong2 u2; };

// ---------------------------------------------------------------------------
// Kernel A — FROZEN R4 version (56 regs, 18.8us, reproduced 6x).
//   P_k[n] = exp( sum_t max(dl_t*A_n, -10) )
//   Q_k[n] = frac0[n] * b0[n] * u0 * eA0[n]   (fw[0] = eA[0] since L>1)
// ---------------------------------------------------------------------------
__global__ __launch_bounds__(256) void pq_kernel(
    const float* __restrict__ u,
    const float* __restrict__ delta,
    const float* __restrict__ bmat,
    const float* __restrict__ Alog)
{
    int bx = blockIdx.x;
    int dblk = bx & 3;           // 4 d-blocks of 256
    int k    = (bx >> 2) & 127;
    int b    = bx >> 9;
    int d    = dblk * 256 + threadIdx.x;

    float A[Nc];
#pragma unroll
    for (int n = 0; n < Nc; ++n) A[n] = -__expf(Alog[n]);

    int base_td = (b * Tc + k * Lc) * Dc + d;

    float S[Nc];
#pragma unroll
    for (int n = 0; n < Nc; ++n) S[n] = 0.0f;

    float dl0 = 0.0f;
#pragma unroll
    for (int t = 0; t < Lc; ++t) {
        float dl = delta[base_td + t * Dc];
        if (t == 0) dl0 = dl;
#pragma unroll
        for (int n = 0; n < Nc; ++n)
            S[n] += fmaxf(dl * A[n], -10.0f);
    }

    float u0 = u[base_td];
    const float4* b0p = reinterpret_cast<const float4*>(bmat + (size_t)base_td * Nc);

    int sbase = k * S_TOT + (b * Dc + d) * Nc;
    float4* Pp = reinterpret_cast<float4*>(g_P + sbase);
    float4* Qp = reinterpret_cast<float4*>(g_Q + sbase);

#pragma unroll
    for (int q = 0; q < 4; ++q) {
        float4 b0 = b0p[q];
        float bv[4] = {b0.x, b0.y, b0.z, b0.w};
        float Pv[4], Qv[4];
#pragma unroll
        for (int i = 0; i < 4; ++i) {
            int n = q * 4 + i;
            float invA = 1.0f / (A[n] + 1e-12f);
            Pv[i] = __expf(S[n]);
            float da0 = fmaxf(dl0 * A[n], -10.0f);
            float eA0 = __expf(da0);
            float frac0 = (fabsf(da0) < 1e-4f) ? (da0 * invA) : (eA0 - 1.0f) * invA;
            Qv[i] = frac0 * bv[i] * u0 * eA0;
        }
        Pp[q] = make_float4(Pv[0], Pv[1], Pv[2], Pv[3]);
        Qp[q] = make_float4(Qv[0], Qv[1], Qv[2], Qv[3]);
    }
}

// ---------------------------------------------------------------------------
// Kernel B: serial scan over the 128 chunks per state.
// ---------------------------------------------------------------------------
__global__ __launch_bounds__(256) void scan_kernel()
{
    int s = blockIdx.x * blockDim.x + threadIdx.x;
    float h = 0.0f;
    for (int kk = 0; kk < Cc; kk += 8) {
        float Pv[8], Qv[8];
#pragma unroll
        for (int j = 0; j < 8; ++j) {
            Pv[j] = g_P[(kk + j) * S_TOT + s];
            Qv[j] = g_Q[(kk + j) * S_TOT + s];
        }
#pragma unroll
        for (int j = 0; j < 8; ++j) {
            g_H0[(kk + j) * S_TOT + s] = h;
            h = fmaf(h, Pv[j], Qv[j]);
        }
    }
}

// ---------------------------------------------------------------------------
// Kernel C: main pass — EXACT R15 body (f32x2 i-loop, direct-MUFU power
// chains, descending cum product, branch-free frac, b@j / c@t_idx, __ldcs)
// at __launch_bounds__(256, 3): the slimmed register footprint (~70-80 live
// regs after f32x2 packing + table removal) should now FIT the 84-reg cap
// that R5's fat kernel spilled under -> 24 warps/SM (+50% MLP) on a
// DRAM-latency-limited kernel.
//   y[t_idx] = sum_n (h0*cumA[t_idx] + PS[j]) * c[t_idx]
// Known numerics: rel_err ~4.5e-4 (deterministic, 2.2x under gate).
// ---------------------------------------------------------------------------
__global__ __launch_bounds__(256, 3) void main_kernel(
    const float* __restrict__ u,
    const float* __restrict__ delta,
    const float* __restrict__ bmat,
    const float* __restrict__ cmat,
    const float* __restrict__ Alog,
    float* __restrict__ y)
{
    const float EXPM10 = 4.5399929762484854e-05f;  // e^-10 (f32)
    const float EXPP10 = 22026.465794806718f;      // e^+10

    int bx = blockIdx.x;
    int dblk = bx & 15;          // 16 d-blocks of 64
    int k    = (bx >> 4) & 127;  // chunk
    int b    = bx >> 11;         // batch

    int tid  = threadIdx.x;
    int ng   = tid & 3;          // n-quad: n = 4*ng .. 4*ng+3
    int dloc = tid >> 2;         // 0..63
    int d    = dblk * 64 + dloc;

    float A[4], invA[4], thr[4];
#pragma unroll
    for (int i = 0; i < 4; ++i) {
        A[i]    = -__expf(Alog[4 * ng + i]);
        invA[i] = 1.0f / (A[i] + 1e-12f);
        thr[i]  = -10.0f / A[i];
    }
    float A0 = A[0];             // leading exponent for this thread's quad

    int base_td = (b * Tc + k * Lc) * Dc + d;

    // Phase 1: dl table (16 regs) + W totals (min-trick)
    float dl[Lc];
    float Wt[4] = {0.0f, 0.0f, 0.0f, 0.0f};
#pragma unroll
    for (int t = 0; t < Lc; ++t) {
        dl[t] = delta[base_td + t * Dc];
#pragma unroll
        for (int i = 0; i < 4; ++i)
            Wt[i] += fminf(dl[t], thr[i]);
    }

    // Prologue: cum = cumA[15] = exp(A*Wtot), packed into pairs
    f32x2 cum2[2];
    cum2[0] = pk2(__expf(A[0] * Wt[0]), __expf(A[1] * Wt[1]));
    cum2[1] = pk2(__expf(A[2] * Wt[2]), __expf(A[3] * Wt[3]));

    f32x2 invA2[2];
    invA2[0] = pk2(invA[0], invA[1]);
    invA2[1] = pk2(invA[2], invA[3]);

    float4 h04 = *reinterpret_cast<const float4*>(
        g_H0 + k * S_TOT + (b * Dc + d) * Nc + 4 * ng);
    f32x2 h02[2];
    h02[0] = pk2(h04.x, h04.y);
    h02[1] = pk2(h04.z, h04.w);

    const f32x2 NEG1 = pk2(-1.0f, -1.0f);

    __shared__ float s_y[Lc * 64];

    f32x2 ps2[2];
    ps2[0] = pk2(0.0f, 0.0f);
    ps2[1] = ps2[0];

#pragma unroll
    for (int j = 0; j < Lc; ++j) {
        int t_idx = Lc - 1 - j;
        float uu = u[base_td + j * Dc];
        V4U2 bU, cU;
        bU.f4 = __ldcs(reinterpret_cast<const float4*>(
            bmat + (size_t)(base_td + j * Dc) * Nc + 4 * ng));
        cU.f4 = __ldcs(reinterpret_cast<const float4*>(
            cmat + (size_t)(base_td + t_idx * Dc) * Nc + 4 * ng));

        // forward: Em1 = exp(dl*A0) direct; Em_{k} = Em_{k-1}*E, E = exp(-dl)
        float E   = __expf(-dl[j]);
        float Em1 = __expf(dl[j] * A0);
        float Em2 = Em1 * E;
        float Em3 = Em2 * E;
        float Em4 = Em3 * E;
        f32x2 eA2p[2];
        eA2p[0] = pk2(fmaxf(Em1, EXPM10), fmaxf(Em2, EXPM10));
        eA2p[1] = pk2(fmaxf(Em3, EXPM10), fmaxf(Em4, EXPM10));

        // backward: Fm1 = exp(-dl*A0) direct; Fm_k = Fm_{k-1}*F, F = exp(+dl)
        float F   = __expf(dl[t_idx]);
        float Fm1 = __expf(-dl[t_idx] * A0);
        float Fm2 = Fm1 * F;
        float Fm3 = Fm2 * F;
        float Fm4 = Fm3 * F;
        f32x2 upd2[2];
        upd2[0] = pk2(fminf(Fm1, EXPP10), fminf(Fm2, EXPP10));
        upd2[1] = pk2(fminf(Fm3, EXPP10), fminf(Fm4, EXPP10));

        f32x2 uu2 = pk2(uu, uu);

        f32x2 acc2 = pk2(0.0f, 0.0f);
#pragma unroll
        for (int p = 0; p < 2; ++p) {
            f32x2 cumA = cum2[p];                       // cumA[t_idx]
            cum2[p] = mul2(cumA, upd2[p]);              // -> cumA[t_idx-1]

            f32x2 em  = add2(eA2p[p], NEG1);            // eA - 1
            f32x2 fr  = mul2(em, invA2[p]);             // frac
            f32x2 bv2 = (p == 0) ? bU.u2.x : bU.u2.y;
            f32x2 cv2 = (p == 0) ? cU.u2.x : cU.u2.y;
            f32x2 bu  = mul2(mul2(fr, bv2), uu2);       // frac*bv*uu
            if (j == Lc - 1)
                ps2[p] = add2(ps2[p], bu);              // fw = 1
            else
                ps2[p] = fma2(bu, eA2p[p], ps2[p]);     // ps += bu*eA
            f32x2 t2 = fma2(h02[p], cumA, ps2[p]);      // h0*cumA + PS
            acc2 = fma2(t2, cv2, acc2);                 // * c, accumulate
        }
        float alo, ahi;
        upk2(acc2, alo, ahi);
        float contrib = alo + ahi;
        // reduce over the 4 n-quad lanes (bits 0..1 of lane id)
        contrib += __shfl_xor_sync(0xffffffffu, contrib, 1, 32);
        contrib += __shfl_xor_sync(0xffffffffu, contrib, 2, 32);
        if (ng == 0) s_y[t_idx * 64 + dloc] = contrib;
    }
    __syncthreads();

    // coalesced y writes: 4 rows of 256
#pragma unroll
    for (int r = 0; r < 4; ++r) {
        int idx = tid + r * 256;
        int tt = idx >> 6;
        int dw = idx & 63;
        y[(b * Tc + k * Lc + tt) * Dc + dblk * 64 + dw] = s_y[idx];
    }
}

// ---------------------------------------------------------------------------
extern "C" void kernel_launch(void* const* d_in, const int* in_sizes, int n_in,
                              void* d_out, int out_size)
{
    const float* u     = (const float*)d_in[0];
    const float* delta = (const float*)d_in[1];
    const float* bmat  = (const float*)d_in[2];
    const float* cmat  = (const float*)d_in[3];
    const float* Alog  = (const float*)d_in[4];
    float* y = (float*)d_out;

    pq_kernel<<<Bc * Cc * 4, 256>>>(u, delta, bmat, Alog);
    scan_kernel<<<S_TOT / 256, 256>>>();
    main_kernel<<<Bc * Cc * 16, 256>>>(u, delta, bmat, cmat, Alog, y);
}

// round 17
// speedup vs baseline: 1.0640x; 1.0640x over previous
#include <cuda_runtime.h>
#include <cuda_bf16.h>

// Problem constants (from reference setup_inputs)
#define Bc 2
#define Tc 2048
#define Dc 1024
#define Nc 16
#define Lc 16
#define Cc 128                 // Tc / Lc
#define S_TOT (Bc*Dc*Nc)       // 32768 states
#define PQ_TOT (Cc*S_TOT)      // 4,194,304

// Scratch (static device arrays — no allocation allowed)
__device__ float g_P[PQ_TOT];
__device__ float g_Q[PQ_TOT];
__device__ float g_H0[PQ_TOT];

// ---- packed f32x2 helpers (sm_103a) ---------------------------------------
typedef unsigned long long f32x2;
__device__ __forceinline__ f32x2 pk2(float lo, float hi) {
    f32x2 r; asm("mov.b64 %0, {%1, %2};" : "=l"(r) : "f"(lo), "f"(hi)); return r;
}
__device__ __forceinline__ void upk2(f32x2 v, float& lo, float& hi) {
    asm("mov.b64 {%0, %1}, %2;" : "=f"(lo), "=f"(hi) : "l"(v));
}
__device__ __forceinline__ f32x2 mul2(f32x2 a, f32x2 b) {
    f32x2 r; asm("mul.rn.f32x2 %0, %1, %2;" : "=l"(r) : "l"(a), "l"(b)); return r;
}
__device__ __forceinline__ f32x2 add2(f32x2 a, f32x2 b) {
    f32x2 r; asm("add.rn.f32x2 %0, %1, %2;" : "=l"(r) : "l"(a), "l"(b)); return r;
}
__device__ __forceinline__ f32x2 fma2(f32x2 a, f32x2 b, f32x2 c) {
    f32x2 r; asm("fma.rn.f32x2 %0, %1, %2, %3;" : "=l"(r) : "l"(a), "l"(b), "l"(c)); return r;
}

union V4U2 { float4 f4; ulonglong2 u2; };

// ---------------------------------------------------------------------------
// Kernel A — FROZEN R4 version (56 regs, 18.8us, reproduced 7x).
//   P_k[n] = exp( sum_t max(dl_t*A_n, -10) )
//   Q_k[n] = frac0[n] * b0[n] * u0 * eA0[n]   (fw[0] = eA[0] since L>1)
// ---------------------------------------------------------------------------
__global__ __launch_bounds__(256) void pq_kernel(
    const float* __restrict__ u,
    const float* __restrict__ delta,
    const float* __restrict__ bmat,
    const float* __restrict__ Alog)
{
    int bx = blockIdx.x;
    int dblk = bx & 3;           // 4 d-blocks of 256
    int k    = (bx >> 2) & 127;
    int b    = bx >> 9;
    int d    = dblk * 256 + threadIdx.x;

    float A[Nc];
#pragma unroll
    for (int n = 0; n < Nc; ++n) A[n] = -__expf(Alog[n]);

    int base_td = (b * Tc + k * Lc) * Dc + d;

    float S[Nc];
#pragma unroll
    for (int n = 0; n < Nc; ++n) S[n] = 0.0f;

    float dl0 = 0.0f;
#pragma unroll
    for (int t = 0; t < Lc; ++t) {
        float dl = delta[base_td + t * Dc];
        if (t == 0) dl0 = dl;
#pragma unroll
        for (int n = 0; n < Nc; ++n)
            S[n] += fmaxf(dl * A[n], -10.0f);
    }

    float u0 = u[base_td];
    const float4* b0p = reinterpret_cast<const float4*>(bmat + (size_t)base_td * Nc);

    int sbase = k * S_TOT + (b * Dc + d) * Nc;
    float4* Pp = reinterpret_cast<float4*>(g_P + sbase);
    float4* Qp = reinterpret_cast<float4*>(g_Q + sbase);

#pragma unroll
    for (int q = 0; q < 4; ++q) {
        float4 b0 = b0p[q];
        float bv[4] = {b0.x, b0.y, b0.z, b0.w};
        float Pv[4], Qv[4];
#pragma unroll
        for (int i = 0; i < 4; ++i) {
            int n = q * 4 + i;
            float invA = 1.0f / (A[n] + 1e-12f);
            Pv[i] = __expf(S[n]);
            float da0 = fmaxf(dl0 * A[n], -10.0f);
            float eA0 = __expf(da0);
            float frac0 = (fabsf(da0) < 1e-4f) ? (da0 * invA) : (eA0 - 1.0f) * invA;
            Qv[i] = frac0 * bv[i] * u0 * eA0;
        }
        Pp[q] = make_float4(Pv[0], Pv[1], Pv[2], Pv[3]);
        Qp[q] = make_float4(Qv[0], Qv[1], Qv[2], Qv[3]);
    }
}

// ---------------------------------------------------------------------------
// Kernel B: serial scan over the 128 chunks per state. P/Q loaded with
// __ldcs (dead after this kernel; evict-first preserves L2 for H0 + main).
// ---------------------------------------------------------------------------
__global__ __launch_bounds__(256) void scan_kernel()
{
    int s = blockIdx.x * blockDim.x + threadIdx.x;
    float h = 0.0f;
    for (int kk = 0; kk < Cc; kk += 8) {
        float Pv[8], Qv[8];
#pragma unroll
        for (int j = 0; j < 8; ++j) {
            Pv[j] = __ldcs(&g_P[(kk + j) * S_TOT + s]);
            Qv[j] = __ldcs(&g_Q[(kk + j) * S_TOT + s]);
        }
#pragma unroll
        for (int j = 0; j < 8; ++j) {
            g_H0[(kk + j) * S_TOT + s] = h;
            h = fmaf(h, Pv[j], Qv[j]);
        }
    }
}

// ---------------------------------------------------------------------------
// Kernel C: main pass — EXACT R15 body (f32x2 i-loop, direct-MUFU power
// chains, descending cum product, branch-free frac, b@j / c@t_idx, __ldcs)
// at the PROVEN (256,2) occupancy. (256,3) spilled and regressed in R16;
// the occupancy lever is conclusively dead — do not raise it again.
// y written with __stcs (never re-read; keep L2 for the b/c streams).
//   y[t_idx] = sum_n (h0*cumA[t_idx] + PS[j]) * c[t_idx]
// Known numerics: rel_err ~4.5e-4 (deterministic, 2.2x under gate).
// ---------------------------------------------------------------------------
__global__ __launch_bounds__(256, 2) void main_kernel(
    const float* __restrict__ u,
    const float* __restrict__ delta,
    const float* __restrict__ bmat,
    const float* __restrict__ cmat,
    const float* __restrict__ Alog,
    float* __restrict__ y)
{
    const float EXPM10 = 4.5399929762484854e-05f;  // e^-10 (f32)
    const float EXPP10 = 22026.465794806718f;      // e^+10

    int bx = blockIdx.x;
    int dblk = bx & 15;          // 16 d-blocks of 64
    int k    = (bx >> 4) & 127;  // chunk
    int b    = bx >> 11;         // batch

    int tid  = threadIdx.x;
    int ng   = tid & 3;          // n-quad: n = 4*ng .. 4*ng+3
    int dloc = tid >> 2;         // 0..63
    int d    = dblk * 64 + dloc;

    float A[4], invA[4], thr[4];
#pragma unroll
    for (int i = 0; i < 4; ++i) {
        A[i]    = -__expf(Alog[4 * ng + i]);
        invA[i] = 1.0f / (A[i] + 1e-12f);
        thr[i]  = -10.0f / A[i];
    }
    float A0 = A[0];             // leading exponent for this thread's quad

    int base_td = (b * Tc + k * Lc) * Dc + d;

    // Phase 1: dl table (16 regs) + W totals (min-trick)
    float dl[Lc];
    float Wt[4] = {0.0f, 0.0f, 0.0f, 0.0f};
#pragma unroll
    for (int t = 0; t < Lc; ++t) {
        dl[t] = delta[base_td + t * Dc];
#pragma unroll
        for (int i = 0; i < 4; ++i)
            Wt[i] += fminf(dl[t], thr[i]);
    }

    // Prologue: cum = cumA[15] = exp(A*Wtot), packed into pairs
    f32x2 cum2[2];
    cum2[0] = pk2(__expf(A[0] * Wt[0]), __expf(A[1] * Wt[1]));
    cum2[1] = pk2(__expf(A[2] * Wt[2]), __expf(A[3] * Wt[3]));

    f32x2 invA2[2];
    invA2[0] = pk2(invA[0], invA[1]);
    invA2[1] = pk2(invA[2], invA[3]);

    float4 h04 = *reinterpret_cast<const float4*>(
        g_H0 + k * S_TOT + (b * Dc + d) * Nc + 4 * ng);
    f32x2 h02[2];
    h02[0] = pk2(h04.x, h04.y);
    h02[1] = pk2(h04.z, h04.w);

    const f32x2 NEG1 = pk2(-1.0f, -1.0f);

    __shared__ float s_y[Lc * 64];

    f32x2 ps2[2];
    ps2[0] = pk2(0.0f, 0.0f);
    ps2[1] = ps2[0];

#pragma unroll
    for (int j = 0; j < Lc; ++j) {
        int t_idx = Lc - 1 - j;
        float uu = u[base_td + j * Dc];
        V4U2 bU, cU;
        bU.f4 = __ldcs(reinterpret_cast<const float4*>(
            bmat + (size_t)(base_td + j * Dc) * Nc + 4 * ng));
        cU.f4 = __ldcs(reinterpret_cast<const float4*>(
            cmat + (size_t)(base_td + t_idx * Dc) * Nc + 4 * ng));

        // forward: Em1 = exp(dl*A0) direct; Em_{k} = Em_{k-1}*E, E = exp(-dl)
        float E   = __expf(-dl[j]);
        float Em1 = __expf(dl[j] * A0);
        float Em2 = Em1 * E;
        float Em3 = Em2 * E;
        float Em4 = Em3 * E;
        f32x2 eA2p[2];
        eA2p[0] = pk2(fmaxf(Em1, EXPM10), fmaxf(Em2, EXPM10));
        eA2p[1] = pk2(fmaxf(Em3, EXPM10), fmaxf(Em4, EXPM10));

        // backward: Fm1 = exp(-dl*A0) direct; Fm_k = Fm_{k-1}*F, F = exp(+dl)
        float F   = __expf(dl[t_idx]);
        float Fm1 = __expf(-dl[t_idx] * A0);
        float Fm2 = Fm1 * F;
        float Fm3 = Fm2 * F;
        float Fm4 = Fm3 * F;
        f32x2 upd2[2];
        upd2[0] = pk2(fminf(Fm1, EXPP10), fminf(Fm2, EXPP10));
        upd2[1] = pk2(fminf(Fm3, EXPP10), fminf(Fm4, EXPP10));

        f32x2 uu2 = pk2(uu, uu);

        f32x2 acc2 = pk2(0.0f, 0.0f);
#pragma unroll
        for (int p = 0; p < 2; ++p) {
            f32x2 cumA = cum2[p];                       // cumA[t_idx]
            cum2[p] = mul2(cumA, upd2[p]);              // -> cumA[t_idx-1]

            f32x2 em  = add2(eA2p[p], NEG1);            // eA - 1
            f32x2 fr  = mul2(em, invA2[p]);             // frac
            f32x2 bv2 = (p == 0) ? bU.u2.x : bU.u2.y;
            f32x2 cv2 = (p == 0) ? cU.u2.x : cU.u2.y;
            f32x2 bu  = mul2(mul2(fr, bv2), uu2);       // frac*bv*uu
            if (j == Lc - 1)
                ps2[p] = add2(ps2[p], bu);              // fw = 1
            else
                ps2[p] = fma2(bu, eA2p[p], ps2[p]);     // ps += bu*eA
            f32x2 t2 = fma2(h02[p], cumA, ps2[p]);      // h0*cumA + PS
            acc2 = fma2(t2, cv2, acc2);                 // * c, accumulate
        }
        float alo, ahi;
        upk2(acc2, alo, ahi);
        float contrib = alo + ahi;
        // reduce over the 4 n-quad lanes (bits 0..1 of lane id)
        contrib += __shfl_xor_sync(0xffffffffu, contrib, 1, 32);
        contrib += __shfl_xor_sync(0xffffffffu, contrib, 2, 32);
        if (ng == 0) s_y[t_idx * 64 + dloc] = contrib;
    }
    __syncthreads();

    // coalesced y writes (streaming — y is never re-read): 4 rows of 256
#pragma unroll
    for (int r = 0; r < 4; ++r) {
        int idx = tid + r * 256;
        int tt = idx >> 6;
        int dw = idx & 63;
        __stcs(&y[(b * Tc + k * Lc + tt) * Dc + dblk * 64 + dw], s_y[idx]);
    }
}

// ---------------------------------------------------------------------------
extern "C" void kernel_launch(void* const* d_in, const int* in_sizes, int n_in,
                              void* d_out, int out_size)
{
    const float* u     = (const float*)d_in[0];
    const float* delta = (const float*)d_in[1];
    const float* bmat  = (const float*)d_in[2];
    const float* cmat  = (const float*)d_in[3];
    const float* Alog  = (const float*)d_in[4];
    float* y = (float*)d_out;

    pq_kernel<<<Bc * Cc * 4, 256>>>(u, delta, bmat, Alog);
    scan_kernel<<<S_TOT / 256, 256>>>();
    main_kernel<<<Bc * Cc * 16, 256>>>(u, delta, bmat, cmat, Alog, y);
}